// round 1
// baseline (speedup 1.0000x reference)
#include <cuda_runtime.h>
#include <math.h>

#define H    160
#define H3   480
#define CC   200
#define TT   20
#define NCH  10
#define NL   160
#define NCLS 16
#define KS   4
#define HS   40        /* H / KS */
#define RPC  120       /* 3*HS rows per CTA */
#define NT   480
#define NW   15
#define NBLK (NCH + KS*NCH + KS + 1)   /* 10 + 40 + 4 + 1 = 55 */

#define NFLAGS ((NL + 1) * NCH + CC + 4)

/* ---- device scratch (allowed: static device globals) ---- */
__device__ float g_S[(NL + 1) * NCH * H];   /* S[l][t][i]: S[0]=x_cat, S[l+1]=layer-l output */
__device__ float g_hg[CC * H];              /* global GRU hidden per step */
__device__ float g_xl[H];                   /* mean hidden of global GRU */
__device__ int   g_flags[NFLAGS];

#define DONE_IDX(l, t) ((l) * NCH + (t))
#define CNTG_IDX(s)    ((NL + 1) * NCH + (s))
#define GDONE_IDX      ((NL + 1) * NCH + CC)

__device__ __forceinline__ float sigm(float v) { return 1.f / (1.f + expf(-v)); }

__device__ __forceinline__ float warp_red(float a) {
#pragma unroll
    for (int o = 16; o > 0; o >>= 1) a += __shfl_down_sync(0xffffffffu, a, o);
    return a;
}

__device__ __forceinline__ float warp_dot160(const float* __restrict__ wrow,
                                             const float* __restrict__ v, int lane) {
    float a = 0.f;
#pragma unroll
    for (int c = 0; c < 5; ++c) a += wrow[c * 32 + lane] * v[c * 32 + lane];
    return warp_red(a);
}

__device__ __forceinline__ void wait_ge(int idx, int tgt) {
    volatile int* p = (volatile int*)&g_flags[idx];
    while (*p < tgt) {}
}

__global__ void zero_flags_kernel() {
    int i = blockIdx.x * blockDim.x + threadIdx.x;
    if (i < NFLAGS) g_flags[i] = 0;
}

__global__ void __launch_bounds__(NT, 1) spectral_kernel(
    const float* __restrict__ x,
    const float* __restrict__ b_wih, const float* __restrict__ b_whh,
    const float* __restrict__ b_bih, const float* __restrict__ b_bhh,
    const float* __restrict__ gw_ih, const float* __restrict__ gw_hh,
    const float* __restrict__ gb_ih, const float* __restrict__ gb_hh,
    const float* __restrict__ g3_wih, const float* __restrict__ g3_whh,
    const float* __restrict__ g3_bih, const float* __restrict__ g3_bhh,
    const float* __restrict__ bn_gamma, const float* __restrict__ bn_beta,
    const float* __restrict__ bn_mean, const float* __restrict__ bn_var,
    const float* __restrict__ fc_w, const float* __restrict__ fc_b,
    const float* __restrict__ reg_w, const float* __restrict__ reg_b,
    float* __restrict__ out)
{
    extern __shared__ float sm[];
    const int tid  = threadIdx.x;
    const int w    = tid >> 5;
    const int lane = tid & 31;
    const int blk  = blockIdx.x;

    /* ================= ROLE A: branch GRUs (blocks 0..9) ================= */
    if (blk < NCH) {
        const int b = blk;
        float* xp = sm;                 /* [TT*H3] */
        float* h  = sm + TT * H3;       /* [H]     */
        float* hp = h + H;              /* [H3]    */

        const float* wih = b_wih + b * H3;        /* [480,1] */
        const float* bih = b_bih + b * H3;
        const float* whh = b_whh + (size_t)b * H3 * H;
        const float* bhh = b_bhh + b * H3;

        for (int idx = tid; idx < TT * H3; idx += NT) {
            int t = idx / H3, j = idx - t * H3;
            xp[idx] = x[b * TT + t] * wih[j] + bih[j];
        }
        if (tid < H) h[tid] = 0.f;
        __syncthreads();

        for (int t = 0; t < TT; ++t) {
            for (int r = w; r < H3; r += NW) {
                float a = warp_dot160(whh + (size_t)r * H, h, lane);
                if (lane == 0) hp[r] = a + bhh[r];
            }
            __syncthreads();
            if (tid < H) {
                const float* xpt = xp + t * H3;
                float r = sigm(xpt[tid]       + hp[tid]);
                float z = sigm(xpt[H + tid]   + hp[H + tid]);
                float n = tanhf(xpt[2*H + tid] + r * hp[2*H + tid]);
                h[tid] = (1.f - z) * n + z * h[tid];
            }
            __syncthreads();
        }
        if (tid < H) g_S[(0 * NCH + b) * H + tid] = h[tid];
        __threadfence();
        __syncthreads();
        if (tid == 0) atomicExch(&g_flags[DONE_IDX(0, b)], KS);
        return;
    }

    /* ================= ROLE B: g3 wavefront (blocks 10..49) ================= */
    if (blk < NCH + KS * NCH) {
        const int g = blk - NCH;
        const int t = g / KS;
        const int c = g - t * KS;

        float* x_in   = sm;             /* [H]   */
        float* h_prev = sm + H;         /* [H]   */
        float* xps    = sm + 2 * H;     /* [RPC] */
        float* hps    = xps + RPC;      /* [RPC] */

        for (int l = 0; l < NL; ++l) {
            if (tid == 0) {
                wait_ge(DONE_IDX(l, t), KS);                 /* x_in = S[l][t] ready   */
                if (t > 0) wait_ge(DONE_IDX(l + 1, t - 1), KS); /* h_prev = S[l+1][t-1] */
            }
            __syncthreads();
            if (tid < H) {
                x_in[tid]   = g_S[(l * NCH + t) * H + tid];
                h_prev[tid] = (t > 0) ? g_S[((l + 1) * NCH + (t - 1)) * H + tid] : 0.f;
            }
            __syncthreads();

            const float* wih = g3_wih + (size_t)l * H3 * H;
            const float* whh = g3_whh + (size_t)l * H3 * H;
            const float* bih = g3_bih + l * H3;
            const float* bhh = g3_bhh + l * H3;

            for (int q = w; q < RPC; q += NW) {
                int j = (q / HS) * H + c * HS + (q % HS);
                float ax = warp_dot160(wih + (size_t)j * H, x_in,   lane);
                float ah = warp_dot160(whh + (size_t)j * H, h_prev, lane);
                if (lane == 0) { xps[q] = ax + bih[j]; hps[q] = ah + bhh[j]; }
            }
            __syncthreads();

            if (tid < HS) {
                float r = sigm(xps[tid]          + hps[tid]);
                float z = sigm(xps[HS + tid]     + hps[HS + tid]);
                float n = tanhf(xps[2*HS + tid]  + r * hps[2*HS + tid]);
                int i = c * HS + tid;
                float hnew = (1.f - z) * n + z * h_prev[i];
                g_S[((l + 1) * NCH + t) * H + i] = hnew;
            }
            __threadfence();
            __syncthreads();
            if (tid == 0) atomicAdd(&g_flags[DONE_IDX(l + 1, t)], 1);
        }
        return;
    }

    /* ================= ROLE C: global GRU (blocks 50..53) ================= */
    if (blk < NCH + KS * NCH + KS) {
        const int c = blk - (NCH + KS * NCH);

        float* whh_s = sm;                      /* [RPC*H] 76.8 KB */
        float* xp_s  = sm + RPC * H;            /* [CC*RPC] 96 KB  */
        float* bhh_s = xp_s + CC * RPC;         /* [RPC] */
        float* hprev = bhh_s + RPC;             /* [H]   */
        float* hp    = hprev + H;               /* [RPC] */

        for (int idx = tid; idx < RPC * H; idx += NT) {
            int q = idx / H, k = idx - q * H;
            int j = (q / HS) * H + c * HS + (q % HS);
            whh_s[idx] = gw_hh[j * H + k];
        }
        for (int idx = tid; idx < CC * RPC; idx += NT) {
            int s = idx / RPC, q = idx - s * RPC;
            int j = (q / HS) * H + c * HS + (q % HS);
            xp_s[idx] = x[s] * gw_ih[j] + gb_ih[j];
        }
        if (tid < RPC) {
            int q = tid;
            int j = (q / HS) * H + c * HS + (q % HS);
            bhh_s[q] = gb_hh[j];
        }
        __syncthreads();

        float hsum = 0.f;
        for (int s = 0; s < CC; ++s) {
            if (s > 0) {
                if (tid == 0) wait_ge(CNTG_IDX(s - 1), KS);
                __syncthreads();
            }
            if (tid < H) hprev[tid] = (s > 0) ? g_hg[(s - 1) * H + tid] : 0.f;
            __syncthreads();

            for (int q = w; q < RPC; q += NW) {
                float a = 0.f;
#pragma unroll
                for (int c2 = 0; c2 < 5; ++c2)
                    a += whh_s[q * H + c2 * 32 + lane] * hprev[c2 * 32 + lane];
                a = warp_red(a);
                if (lane == 0) hp[q] = a + bhh_s[q];
            }
            __syncthreads();

            if (tid < HS) {
                const float* xpt = xp_s + s * RPC;
                float r = sigm(xpt[tid]         + hp[tid]);
                float z = sigm(xpt[HS + tid]    + hp[HS + tid]);
                float n = tanhf(xpt[2*HS + tid] + r * hp[2*HS + tid]);
                float hnew = (1.f - z) * n + z * hprev[c * HS + tid];
                g_hg[s * H + c * HS + tid] = hnew;
                hsum += hnew;
            }
            __threadfence();
            __syncthreads();
            if (tid == 0) atomicAdd(&g_flags[CNTG_IDX(s)], 1);
        }
        if (tid < HS) g_xl[c * HS + tid] = hsum * (1.f / CC);
        __threadfence();
        __syncthreads();
        if (tid == 0) atomicAdd(&g_flags[GDONE_IDX], 1);
        return;
    }

    /* ================= ROLE D: epilogue (block 54) ================= */
    {
        if (tid == 0) {
            for (int t = 0; t < NCH; ++t) wait_ge(DONE_IDX(NL, t), KS);
            wait_ge(GDONE_IDX, KS);
        }
        __syncthreads();

        float* xr = sm;   /* [H] */
        if (tid < H) {
            float m = 0.f;
            for (int t = 0; t < NCH; ++t) m += g_S[(NL * NCH + t) * H + tid];
            m *= (1.f / NCH);
            m = fmaxf(m, 0.f);                       /* relu(mean) */
            float xnew = g_xl[tid] * m;
            float xb = (xnew - bn_mean[tid]) * rsqrtf(bn_var[tid] + 1e-5f)
                       * bn_gamma[tid] + bn_beta[tid];
            xr[tid] = fmaxf(xb, 0.f);
        }
        __syncthreads();

        for (int r = w; r < NCLS + CC; r += NW) {
            const float* wrow;
            float bias;
            if (r < NCLS) { wrow = fc_w + r * H;            bias = fc_b[r]; }
            else          { wrow = reg_w + (r - NCLS) * H;  bias = reg_b[r - NCLS]; }
            float a = warp_dot160(wrow, xr, lane);
            if (lane == 0) out[r] = a + bias;
        }
        return;
    }
}

extern "C" void kernel_launch(void* const* d_in, const int* in_sizes, int n_in,
                              void* d_out, int out_size) {
    const float* x        = (const float*)d_in[0];
    const float* b_wih    = (const float*)d_in[1];
    const float* b_whh    = (const float*)d_in[2];
    const float* b_bih    = (const float*)d_in[3];
    const float* b_bhh    = (const float*)d_in[4];
    const float* gw_ih    = (const float*)d_in[5];
    const float* gw_hh    = (const float*)d_in[6];
    const float* gb_ih    = (const float*)d_in[7];
    const float* gb_hh    = (const float*)d_in[8];
    const float* g3_wih   = (const float*)d_in[9];
    const float* g3_whh   = (const float*)d_in[10];
    const float* g3_bih   = (const float*)d_in[11];
    const float* g3_bhh   = (const float*)d_in[12];
    const float* bn_gamma = (const float*)d_in[13];
    const float* bn_beta  = (const float*)d_in[14];
    const float* bn_mean  = (const float*)d_in[15];
    const float* bn_var   = (const float*)d_in[16];
    const float* fc_w     = (const float*)d_in[17];
    const float* fc_b     = (const float*)d_in[18];
    const float* reg_w    = (const float*)d_in[19];
    const float* reg_b    = (const float*)d_in[20];
    float* out = (float*)d_out;

    /* global-GRU role smem: (RPC*H + CC*RPC + RPC + H + RPC) floats */
    const int smem_bytes = (RPC * H + CC * RPC + RPC + H + RPC) * (int)sizeof(float);
    cudaFuncSetAttribute(spectral_kernel,
                         cudaFuncAttributeMaxDynamicSharedMemorySize, smem_bytes);

    zero_flags_kernel<<<(NFLAGS + 255) / 256, 256>>>();
    spectral_kernel<<<NBLK, NT, smem_bytes>>>(
        x, b_wih, b_whh, b_bih, b_bhh,
        gw_ih, gw_hh, gb_ih, gb_hh,
        g3_wih, g3_whh, g3_bih, g3_bhh,
        bn_gamma, bn_beta, bn_mean, bn_var,
        fc_w, fc_b, reg_w, reg_b, out);
}